// round 7
// baseline (speedup 1.0000x reference)
#include <cuda_runtime.h>
#include <cuda_fp16.h>

#define SHIFTV 4
#define HEADS 4
#define NW 8          // windows per CTA
#define NTHREADS 512

// pitches in __half units; all row strides 16B-aligned & ldmatrix-conflict-free
#define XP 136   // Xs (input / attention-output overlay) [64][128]
#define WQP 136  // WqkvT [384][128]
#define WPP 136  // WprojT [128][128]
#define QP 40    // Qs/Ks per head [64][32]
#define VP 72    // Vt per head [32 d-rows][64 tokens] (+pad)

#define H_WQ   (384*WQP)
#define H_WP   (128*WPP)
#define H_X    (64*XP)
#define H_Q    (HEADS*64*QP)
#define H_K    (HEADS*64*QP)
#define H_V    (HEADS*32*VP)
#define SMEM_HALVES (H_WQ + H_WP + H_X + H_Q + H_K + H_V)
#define SMEM_FLOATS (225*HEADS + 384 + 128)
#define SMEM_BYTES  (SMEM_HALVES*2 + SMEM_FLOATS*4)

__device__ __align__(16) __half g_qkvT[384*128];
__device__ __align__(16) __half g_projT[128*128];

__global__ void prep_qkv(const float* __restrict__ w) {
    int i = blockIdx.x * 256 + threadIdx.x;
    if (i < 384*128) {
        int n = i >> 7, k = i & 127;
        g_qkvT[i] = __float2half_rn(w[k*384 + n]);
    }
}
__global__ void prep_proj(const float* __restrict__ w) {
    int i = blockIdx.x * 256 + threadIdx.x;
    if (i < 128*128) {
        int n = i >> 7, k = i & 127;
        g_projT[i] = __float2half_rn(w[k*128 + n]);
    }
}

__device__ __forceinline__ void mma_f16(float& c0, float& c1, float& c2, float& c3,
                                        unsigned a0, unsigned a1, unsigned a2, unsigned a3,
                                        unsigned b0, unsigned b1) {
    asm volatile(
        "mma.sync.aligned.m16n8k16.row.col.f32.f16.f16.f32 "
        "{%0,%1,%2,%3},{%4,%5,%6,%7},{%8,%9},{%0,%1,%2,%3};\n"
        : "+f"(c0), "+f"(c1), "+f"(c2), "+f"(c3)
        : "r"(a0), "r"(a1), "r"(a2), "r"(a3), "r"(b0), "r"(b1));
}

__device__ __forceinline__ void ldsm_x4(unsigned& r0, unsigned& r1,
                                        unsigned& r2, unsigned& r3, unsigned addr) {
    asm volatile("ldmatrix.sync.aligned.m8n8.x4.shared.b16 {%0,%1,%2,%3}, [%4];\n"
                 : "=r"(r0), "=r"(r1), "=r"(r2), "=r"(r3) : "r"(addr));
}

__device__ __forceinline__ unsigned s2u(const void* p) {
    return (unsigned)__cvta_generic_to_shared(p);
}

__device__ __forceinline__ float bias_at(const float* Bs, int h, int i, int j) {
    int idx = ((i >> 3) - (j >> 3) + 7) * 15 + ((i & 7) - (j & 7) + 7);
    return Bs[idx * HEADS + h];
}

__global__ __launch_bounds__(NTHREADS, 1) void swin_win_attn_kernel(
    const float* __restrict__ x, const float* __restrict__ qkv_b,
    const float* __restrict__ proj_b, const float* __restrict__ bias_table,
    float* __restrict__ out)
{
    extern __shared__ char smem_raw[];
    __half* Wq = reinterpret_cast<__half*>(smem_raw);
    __half* Wp = Wq + H_WQ;
    __half* Xs = Wp + H_WP;      // input window; later attention output O
    __half* Qs = Xs + H_X;
    __half* Ks = Qs + H_Q;
    __half* Vt = Ks + H_K;
    float*  Bs = reinterpret_cast<float*>(Vt + H_V);
    float*  qb = Bs + 225*HEADS;
    float*  pb = qb + 384;

    const int tid = threadIdx.x, lane = tid & 31, wid = tid >> 5;
    const int g = lane >> 2, tg = lane & 3;

    // ldmatrix per-lane address offsets
    const int rA = ((lane >> 3) & 1) * 8 + (lane & 7);  // A: row within 16
    const int cA = (lane >> 4) * 8;                     // A: k-half
    const int rB = ((lane >> 4) & 1) * 8 + (lane & 7);  // B: n within 16 (two 8-blocks)
    const int cB = ((lane >> 3) & 1) * 8;               // B: k-half

    // ---- one-time per CTA: resident weights (vectorized) + biases ----
    {
        const uint4* src = reinterpret_cast<const uint4*>(g_qkvT);
        for (int i = tid; i < 384*16; i += NTHREADS) {
            int r = i >> 4, c = i & 15;
            *reinterpret_cast<uint4*>(Wq + r*WQP + c*8) = src[i];
        }
        const uint4* src2 = reinterpret_cast<const uint4*>(g_projT);
        for (int i = tid; i < 128*16; i += NTHREADS) {
            int r = i >> 4, c = i & 15;
            *reinterpret_cast<uint4*>(Wp + r*WPP + c*8) = src2[i];
        }
        for (int i = tid; i < 225*HEADS; i += NTHREADS) Bs[i] = bias_table[i];
        if (tid < 384) qb[tid] = qkv_b[tid];
        if (tid < 128) pb[tid] = proj_b[tid];
    }

    const float scale = 0.17677669529663687f;  // 32^-0.5

    // register-pipelined gather: this thread's 4 tokens x 8 halves
    unsigned hreg[8];
    const int c4 = lane * 4;            // column base (x4 floats)
    auto gather_regs = [&](int widx) {
        int bb = widx >> 12, wh = (widx >> 6) & 63, ww = widx & 63;
        #pragma unroll
        for (int k = 0; k < 4; ++k) {
            int t = wid + k * 16;       // token 0..63
            int i = t >> 3, j = t & 7;
            int gr = (wh*8 + i + SHIFTV) & 511;
            int gc = (ww*8 + j + SHIFTV) & 511;
            float4 v = *reinterpret_cast<const float4*>(
                x + (((size_t)bb*512 + gr)*512 + gc)*128 + c4);
            __half2 h0 = __floats2half2_rn(v.x, v.y);
            __half2 h1 = __floats2half2_rn(v.z, v.w);
            hreg[k*2]   = *reinterpret_cast<unsigned*>(&h0);
            hreg[k*2+1] = *reinterpret_cast<unsigned*>(&h1);
        }
    };
    auto store_regs = [&]() {
        #pragma unroll
        for (int k = 0; k < 4; ++k) {
            int t = wid + k * 16;
            *reinterpret_cast<unsigned*>(Xs + t*XP + c4)     = hreg[k*2];
            *reinterpret_cast<unsigned*>(Xs + t*XP + c4 + 2) = hreg[k*2+1];
        }
    };

    gather_regs(blockIdx.x * NW);

    for (int wi = 0; wi < NW; ++wi) {
        const int widx = blockIdx.x * NW + wi;
        const int b = widx >> 12, wh = (widx >> 6) & 63, ww = widx & 63;

        __syncthreads();   // Xs free (prev proj done); first iter: weights loaded
        store_regs();
        __syncthreads();

        // ---- QKV: [64x128]@[128x384]; warp = 32 rows x 48 cols ----
        {
            const int rh = wid & 1, cb = (wid >> 1) * 48;
            const unsigned aBase = s2u(Xs) + ((rh*32 + rA)*XP + cA) * 2;
            const unsigned bBase = s2u(Wq) + ((cb + rB)*WQP + cB) * 2;

            float c[2][6][4];
            #pragma unroll
            for (int mt = 0; mt < 2; ++mt)
                #pragma unroll
                for (int p = 0; p < 6; ++p)
                    c[mt][p][0] = c[mt][p][1] = c[mt][p][2] = c[mt][p][3] = 0.f;

            #pragma unroll
            for (int ks = 0; ks < 8; ++ks) {
                int k0 = ks * 16;
                unsigned a[2][4];
                ldsm_x4(a[0][0], a[0][1], a[0][2], a[0][3], aBase + k0*2);
                ldsm_x4(a[1][0], a[1][1], a[1][2], a[1][3], aBase + (16*XP + k0)*2);
                #pragma unroll
                for (int pp = 0; pp < 3; ++pp) {
                    unsigned bf[4];
                    ldsm_x4(bf[0], bf[1], bf[2], bf[3], bBase + (pp*16*WQP + k0)*2);
                    #pragma unroll
                    for (int mt = 0; mt < 2; ++mt) {
                        mma_f16(c[mt][2*pp][0], c[mt][2*pp][1], c[mt][2*pp][2], c[mt][2*pp][3],
                                a[mt][0], a[mt][1], a[mt][2], a[mt][3], bf[0], bf[1]);
                        mma_f16(c[mt][2*pp+1][0], c[mt][2*pp+1][1], c[mt][2*pp+1][2], c[mt][2*pp+1][3],
                                a[mt][0], a[mt][1], a[mt][2], a[mt][3], bf[2], bf[3]);
                    }
                }
            }
            // epilogue: route to Q / K / V(T) with bias
            #pragma unroll
            for (int p = 0; p < 6; ++p) {
                int col = cb + p*8 + 2*tg;
                int mat = col >> 7, head = (col >> 5) & 3, d = col & 31;
                float b0 = qb[col], b1 = qb[col + 1];
                #pragma unroll
                for (int mt = 0; mt < 2; ++mt) {
                    int row = rh*32 + mt*16 + g;
                    if (mat == 0) {
                        __half* Qh = Qs + head*64*QP;
                        *reinterpret_cast<__half2*>(Qh + row*QP + d) =
                            __floats2half2_rn(c[mt][p][0] + b0, c[mt][p][1] + b1);
                        *reinterpret_cast<__half2*>(Qh + (row+8)*QP + d) =
                            __floats2half2_rn(c[mt][p][2] + b0, c[mt][p][3] + b1);
                    } else if (mat == 1) {
                        __half* Kh = Ks + head*64*QP;
                        *reinterpret_cast<__half2*>(Kh + row*QP + d) =
                            __floats2half2_rn(c[mt][p][0] + b0, c[mt][p][1] + b1);
                        *reinterpret_cast<__half2*>(Kh + (row+8)*QP + d) =
                            __floats2half2_rn(c[mt][p][2] + b0, c[mt][p][3] + b1);
                    } else {
                        __half* Vh = Vt + head*32*VP;
                        Vh[d*VP + row]         = __float2half_rn(c[mt][p][0] + b0);
                        Vh[(d+1)*VP + row]     = __float2half_rn(c[mt][p][1] + b1);
                        Vh[d*VP + row + 8]     = __float2half_rn(c[mt][p][2] + b0);
                        Vh[(d+1)*VP + row + 8] = __float2half_rn(c[mt][p][3] + b1);
                    }
                }
            }
        }
        __syncthreads();

        // prefetch next window's input into registers (hidden behind attn+proj)
        if (wi + 1 < NW) gather_regs(widx + 1);

        // ---- attention: warp = (head, 16-row quarter); softmax in registers ----
        {
            const int h = wid >> 2, r0 = (wid & 3) * 16;
            const __half* Qh = Qs + h*64*QP;
            const __half* Kh = Ks + h*64*QP;
            const __half* Vh = Vt + h*32*VP;
            const unsigned qBase = s2u(Qh) + ((r0 + rA)*QP + cA) * 2;
            const unsigned kBase = s2u(Kh) + (rB*QP + cB) * 2;
            const unsigned vBase = s2u(Vh) + (rB*VP + cB) * 2;

            float s[8][4];
            #pragma unroll
            for (int nt = 0; nt < 8; ++nt)
                s[nt][0] = s[nt][1] = s[nt][2] = s[nt][3] = 0.f;

            #pragma unroll
            for (int kt = 0; kt < 2; ++kt) {
                int k0 = kt * 16;
                unsigned a[4];
                ldsm_x4(a[0], a[1], a[2], a[3], qBase + k0*2);
                #pragma unroll
                for (int ntp = 0; ntp < 4; ++ntp) {
                    unsigned bf[4];
                    ldsm_x4(bf[0], bf[1], bf[2], bf[3], kBase + (ntp*16*QP + k0)*2);
                    mma_f16(s[2*ntp][0], s[2*ntp][1], s[2*ntp][2], s[2*ntp][3],
                            a[0], a[1], a[2], a[3], bf[0], bf[1]);
                    mma_f16(s[2*ntp+1][0], s[2*ntp+1][1], s[2*ntp+1][2], s[2*ntp+1][3],
                            a[0], a[1], a[2], a[3], bf[2], bf[3]);
                }
            }

            // scale + bias + rowwise softmax (4 lanes per row via shfl)
            #pragma unroll
            for (int rr = 0; rr < 2; ++rr) {
                int row = r0 + g + rr*8;
                float m = -1e30f;
                #pragma unroll
                for (int nt = 0; nt < 8; ++nt) {
                    #pragma unroll
                    for (int q = 0; q < 2; ++q) {
                        int col = nt*8 + 2*tg + q;
                        float v = s[nt][rr*2+q] * scale + bias_at(Bs, h, row, col);
                        s[nt][rr*2+q] = v;
                        m = fmaxf(m, v);
                    }
                }
                m = fmaxf(m, __shfl_xor_sync(0xffffffffu, m, 1));
                m = fmaxf(m, __shfl_xor_sync(0xffffffffu, m, 2));
                float sum = 0.f;
                #pragma unroll
                for (int nt = 0; nt < 8; ++nt) {
                    #pragma unroll
                    for (int q = 0; q < 2; ++q) {
                        float e = __expf(s[nt][rr*2+q] - m);
                        s[nt][rr*2+q] = e;
                        sum += e;
                    }
                }
                sum += __shfl_xor_sync(0xffffffffu, sum, 1);
                sum += __shfl_xor_sync(0xffffffffu, sum, 2);
                float inv = 1.0f / sum;
                #pragma unroll
                for (int nt = 0; nt < 8; ++nt) {
                    s[nt][rr*2+0] *= inv;
                    s[nt][rr*2+1] *= inv;
                }
            }

            // repack probs (c-frag) as A-frags for PV
            unsigned af[4][4];
            #pragma unroll
            for (int kt = 0; kt < 4; ++kt) {
                __half2 h0 = __floats2half2_rn(s[2*kt][0],   s[2*kt][1]);
                __half2 h1 = __floats2half2_rn(s[2*kt][2],   s[2*kt][3]);
                __half2 h2 = __floats2half2_rn(s[2*kt+1][0], s[2*kt+1][1]);
                __half2 h3 = __floats2half2_rn(s[2*kt+1][2], s[2*kt+1][3]);
                af[kt][0] = *reinterpret_cast<unsigned*>(&h0);
                af[kt][1] = *reinterpret_cast<unsigned*>(&h1);
                af[kt][2] = *reinterpret_cast<unsigned*>(&h2);
                af[kt][3] = *reinterpret_cast<unsigned*>(&h3);
            }

            // O = P @ V  (B-frags from Vt via ldmatrix)
            float o[4][4];
            #pragma unroll
            for (int nt = 0; nt < 4; ++nt)
                o[nt][0] = o[nt][1] = o[nt][2] = o[nt][3] = 0.f;

            #pragma unroll
            for (int kt = 0; kt < 4; ++kt) {
                #pragma unroll
                for (int ntp = 0; ntp < 2; ++ntp) {
                    unsigned bf[4];
                    ldsm_x4(bf[0], bf[1], bf[2], bf[3], vBase + (ntp*16*VP + kt*16)*2);
                    mma_f16(o[2*ntp][0], o[2*ntp][1], o[2*ntp][2], o[2*ntp][3],
                            af[kt][0], af[kt][1], af[kt][2], af[kt][3], bf[0], bf[1]);
                    mma_f16(o[2*ntp+1][0], o[2*ntp+1][1], o[2*ntp+1][2], o[2*ntp+1][3],
                            af[kt][0], af[kt][1], af[kt][2], af[kt][3], bf[2], bf[3]);
                }
            }
            // write O into Xs (input dead now)
            #pragma unroll
            for (int nt = 0; nt < 4; ++nt) {
                int col = h*32 + nt*8 + 2*tg;
                int row = r0 + g;
                *reinterpret_cast<__half2*>(Xs + row*XP + col) =
                    __floats2half2_rn(o[nt][0], o[nt][1]);
                *reinterpret_cast<__half2*>(Xs + (row+8)*XP + col) =
                    __floats2half2_rn(o[nt][2], o[nt][3]);
            }
        }
        __syncthreads();

        // ---- proj: [64x128]@[128x128]; warp = 16 rows x 32 cols; scatter store ----
        {
            const int mh = wid >> 2, nq = wid & 3;
            const unsigned aBase = s2u(Xs) + ((mh*16 + rA)*XP + cA) * 2;
            const unsigned bBase = s2u(Wp) + ((nq*32 + rB)*WPP + cB) * 2;

            float c[4][4];
            #pragma unroll
            for (int nt = 0; nt < 4; ++nt)
                c[nt][0] = c[nt][1] = c[nt][2] = c[nt][3] = 0.f;

            #pragma unroll
            for (int ks = 0; ks < 8; ++ks) {
                int k0 = ks * 16;
                unsigned a[4];
                ldsm_x4(a[0], a[1], a[2], a[3], aBase + k0*2);
                #pragma unroll
                for (int ntp = 0; ntp < 2; ++ntp) {
                    unsigned bf[4];
                    ldsm_x4(bf[0], bf[1], bf[2], bf[3], bBase + (ntp*16*WPP + k0)*2);
                    mma_f16(c[2*ntp][0], c[2*ntp][1], c[2*ntp][2], c[2*ntp][3],
                            a[0], a[1], a[2], a[3], bf[0], bf[1]);
                    mma_f16(c[2*ntp+1][0], c[2*ntp+1][1], c[2*ntp+1][2], c[2*ntp+1][3],
                            a[0], a[1], a[2], a[3], bf[2], bf[3]);
                }
            }
            #pragma unroll
            for (int nt = 0; nt < 4; ++nt) {
                int col = nq*32 + nt*8 + 2*tg;
                float b0 = pb[col], b1 = pb[col + 1];
                #pragma unroll
                for (int rr = 0; rr < 2; ++rr) {
                    int t = mh*16 + g + rr*8;
                    int i = t >> 3, j = t & 7;
                    int gr = (wh*8 + i + SHIFTV) & 511;
                    int gc = (ww*8 + j + SHIFTV) & 511;
                    float2 st;
                    st.x = c[nt][rr*2+0] + b0;
                    st.y = c[nt][rr*2+1] + b1;
                    *reinterpret_cast<float2*>(
                        out + (((size_t)b*512 + gr)*512 + gc)*128 + col) = st;
                }
            }
        }
    }
}

extern "C" void kernel_launch(void* const* d_in, const int* in_sizes, int n_in,
                              void* d_out, int out_size)
{
    const float* x          = (const float*)d_in[0];
    const float* qkv_w      = (const float*)d_in[1];
    const float* qkv_b      = (const float*)d_in[2];
    const float* proj_w     = (const float*)d_in[3];
    const float* proj_b     = (const float*)d_in[4];
    const float* bias_table = (const float*)d_in[5];
    float* out = (float*)d_out;

    prep_qkv<<<(384*128 + 255)/256, 256>>>(qkv_w);
    prep_proj<<<(128*128 + 255)/256, 256>>>(proj_w);

    cudaFuncSetAttribute(swin_win_attn_kernel,
                         cudaFuncAttributeMaxDynamicSharedMemorySize, SMEM_BYTES);
    swin_win_attn_kernel<<<16384/NW, NTHREADS, SMEM_BYTES>>>(
        x, qkv_b, proj_b, bias_table, out);
}

// round 8
// speedup vs baseline: 1.2396x; 1.2396x over previous
#include <cuda_runtime.h>
#include <cuda_fp16.h>

#define SHIFTV 4
#define HEADS 4
#define NW 8
#define NTHREADS 512

#define XP 136
#define WQP 136
#define WPP 136
#define QP 40
#define VP 72

#define H_WQ (384*WQP)
#define H_WP (128*WPP)
#define H_X  (64*XP)
#define H_Q  (HEADS*64*QP)
#define H_K  (HEADS*64*QP)
#define H_V  (HEADS*32*VP)
#define SMEM_HALVES (H_WQ+H_WP+H_X+H_Q+H_K+H_V)
#define SMEM_BYTES  (SMEM_HALVES*2 + (384+128)*4)

__device__ __forceinline__ void mma_f16(float& c0, float& c1, float& c2, float& c3,
                                        unsigned a0, unsigned a1, unsigned a2, unsigned a3,
                                        unsigned b0, unsigned b1) {
    asm volatile(
        "mma.sync.aligned.m16n8k16.row.col.f32.f16.f16.f32 "
        "{%0,%1,%2,%3},{%4,%5,%6,%7},{%8,%9},{%0,%1,%2,%3};\n"
        : "+f"(c0), "+f"(c1), "+f"(c2), "+f"(c3)
        : "r"(a0), "r"(a1), "r"(a2), "r"(a3), "r"(b0), "r"(b1));
}
__device__ __forceinline__ void ldsm_x4(unsigned& r0, unsigned& r1,
                                        unsigned& r2, unsigned& r3, unsigned addr) {
    asm volatile("ldmatrix.sync.aligned.m8n8.x4.shared.b16 {%0,%1,%2,%3}, [%4];\n"
                 : "=r"(r0), "=r"(r1), "=r"(r2), "=r"(r3) : "r"(addr));
}
__device__ __forceinline__ unsigned s2u(const void* p) {
    return (unsigned)__cvta_generic_to_shared(p);
}
__device__ __forceinline__ int bidx(int i, int j) {
    return ((i >> 3) - (j >> 3) + 7) * 15 + ((i & 7) - (j & 7) + 7);
}

__global__ __launch_bounds__(NTHREADS, 1) void swin_win_attn_kernel(
    const float* __restrict__ x, const float* __restrict__ qkv_w,
    const float* __restrict__ qkv_b, const float* __restrict__ proj_w,
    const float* __restrict__ proj_b, const float* __restrict__ bias_table,
    float* __restrict__ out)
{
    extern __shared__ char smem_raw[];
    __half* Wq = reinterpret_cast<__half*>(smem_raw);
    __half* Wp = Wq + H_WQ;
    __half* Xs = Wp + H_WP;      // input window; later attention output O
    __half* Qs = Xs + H_X;
    __half* Ks = Qs + H_Q;
    __half* Vt = Ks + H_K;
    float*  qb = reinterpret_cast<float*>(Vt + H_V);
    float*  pb = qb + 384;

    const int tid = threadIdx.x, lane = tid & 31, wid = tid >> 5;
    const int g = lane >> 2, tg = lane & 3;

    const int rA = ((lane >> 3) & 1) * 8 + (lane & 7);
    const int cA = (lane >> 4) * 8;
    const int rB = ((lane >> 4) & 1) * 8 + (lane & 7);
    const int cB = ((lane >> 3) & 1) * 8;

    // ---- one-time: weights fp32->fp16 transposed into SMEM (coalesced reads) ----
    for (int i = tid; i < 128*96; i += NTHREADS) {      // qkv: [128k][384n]
        int k = i / 96, n4 = (i % 96) * 4;
        float4 v = *reinterpret_cast<const float4*>(qkv_w + k*384 + n4);
        Wq[(n4+0)*WQP + k] = __float2half_rn(v.x);
        Wq[(n4+1)*WQP + k] = __float2half_rn(v.y);
        Wq[(n4+2)*WQP + k] = __float2half_rn(v.z);
        Wq[(n4+3)*WQP + k] = __float2half_rn(v.w);
    }
    for (int i = tid; i < 128*32; i += NTHREADS) {      // proj: [128k][128n]
        int k = i >> 5, n4 = (i & 31) * 4;
        float4 v = *reinterpret_cast<const float4*>(proj_w + k*128 + n4);
        Wp[(n4+0)*WPP + k] = __float2half_rn(v.x);
        Wp[(n4+1)*WPP + k] = __float2half_rn(v.y);
        Wp[(n4+2)*WPP + k] = __float2half_rn(v.z);
        Wp[(n4+3)*WPP + k] = __float2half_rn(v.w);
    }
    if (tid < 384) qb[tid] = qkv_b[tid];
    if (tid < 128) pb[tid] = proj_b[tid];

    // ---- one-time: this thread's bias fragment (window-invariant) ----
    __half2 barr[2][8];
    {
        int h = wid >> 2, r0 = (wid & 3) * 16;
        #pragma unroll
        for (int rr = 0; rr < 2; ++rr)
            #pragma unroll
            for (int nt = 0; nt < 8; ++nt) {
                int row = r0 + g + rr*8, c0 = nt*8 + 2*tg;
                barr[rr][nt] = __floats2half2_rn(
                    bias_table[bidx(row, c0)*HEADS + h],
                    bias_table[bidx(row, c0+1)*HEADS + h]);
            }
    }

    const float scale = 0.17677669529663687f;

    // register-pipelined gather
    unsigned hreg[8];
    const int c4 = lane * 4;
    auto gather_regs = [&](int widx) {
        int bb = widx >> 12, wh = (widx >> 6) & 63, ww = widx & 63;
        #pragma unroll
        for (int k = 0; k < 4; ++k) {
            int t = wid + k * 16;
            int i = t >> 3, j = t & 7;
            int gr = (wh*8 + i + SHIFTV) & 511;
            int gc = (ww*8 + j + SHIFTV) & 511;
            float4 v = *reinterpret_cast<const float4*>(
                x + (((size_t)bb*512 + gr)*512 + gc)*128 + c4);
            __half2 h0 = __floats2half2_rn(v.x, v.y);
            __half2 h1 = __floats2half2_rn(v.z, v.w);
            hreg[k*2]   = *reinterpret_cast<unsigned*>(&h0);
            hreg[k*2+1] = *reinterpret_cast<unsigned*>(&h1);
        }
    };
    auto store_regs = [&]() {
        #pragma unroll
        for (int k = 0; k < 4; ++k) {
            int t = wid + k * 16;
            *reinterpret_cast<unsigned*>(Xs + t*XP + c4)     = hreg[k*2];
            *reinterpret_cast<unsigned*>(Xs + t*XP + c4 + 2) = hreg[k*2+1];
        }
    };

    gather_regs(blockIdx.x * NW);

    for (int wi = 0; wi < NW; ++wi) {
        const int widx = blockIdx.x * NW + wi;
        const int b = widx >> 12, wh = (widx >> 6) & 63, ww = widx & 63;

        __syncthreads();   // Xs free / weights ready
        store_regs();
        __syncthreads();

        // ---- QKV: warp = 32 rows x 48 cols ----
        {
            const int rh = wid & 1, cb = (wid >> 1) * 48;
            const unsigned aBase = s2u(Xs) + ((rh*32 + rA)*XP + cA) * 2;
            const unsigned bBase = s2u(Wq) + ((cb + rB)*WQP + cB) * 2;

            float c[2][6][4];
            #pragma unroll
            for (int mt = 0; mt < 2; ++mt)
                #pragma unroll
                for (int p = 0; p < 6; ++p)
                    c[mt][p][0] = c[mt][p][1] = c[mt][p][2] = c[mt][p][3] = 0.f;

            #pragma unroll
            for (int ks = 0; ks < 8; ++ks) {
                int k0 = ks * 16;
                unsigned a[2][4];
                ldsm_x4(a[0][0], a[0][1], a[0][2], a[0][3], aBase + k0*2);
                ldsm_x4(a[1][0], a[1][1], a[1][2], a[1][3], aBase + (16*XP + k0)*2);
                #pragma unroll
                for (int pp = 0; pp < 3; ++pp) {
                    unsigned bf[4];
                    ldsm_x4(bf[0], bf[1], bf[2], bf[3], bBase + (pp*16*WQP + k0)*2);
                    #pragma unroll
                    for (int mt = 0; mt < 2; ++mt) {
                        mma_f16(c[mt][2*pp][0], c[mt][2*pp][1], c[mt][2*pp][2], c[mt][2*pp][3],
                                a[mt][0], a[mt][1], a[mt][2], a[mt][3], bf[0], bf[1]);
                        mma_f16(c[mt][2*pp+1][0], c[mt][2*pp+1][1], c[mt][2*pp+1][2], c[mt][2*pp+1][3],
                                a[mt][0], a[mt][1], a[mt][2], a[mt][3], bf[2], bf[3]);
                    }
                }
            }
            #pragma unroll
            for (int p = 0; p < 6; ++p) {
                int col = cb + p*8 + 2*tg;
                int mat = col >> 7, head = (col >> 5) & 3, d = col & 31;
                float b0 = qb[col], b1 = qb[col + 1];
                #pragma unroll
                for (int mt = 0; mt < 2; ++mt) {
                    int row = rh*32 + mt*16 + g;
                    if (mat == 0) {
                        __half* Qh = Qs + head*64*QP;
                        *reinterpret_cast<__half2*>(Qh + row*QP + d) =
                            __floats2half2_rn(c[mt][p][0] + b0, c[mt][p][1] + b1);
                        *reinterpret_cast<__half2*>(Qh + (row+8)*QP + d) =
                            __floats2half2_rn(c[mt][p][2] + b0, c[mt][p][3] + b1);
                    } else if (mat == 1) {
                        __half* Kh = Ks + head*64*QP;
                        *reinterpret_cast<__half2*>(Kh + row*QP + d) =
                            __floats2half2_rn(c[mt][p][0] + b0, c[mt][p][1] + b1);
                        *reinterpret_cast<__half2*>(Kh + (row+8)*QP + d) =
                            __floats2half2_rn(c[mt][p][2] + b0, c[mt][p][3] + b1);
                    } else {
                        __half* Vh = Vt + head*32*VP;
                        Vh[d*VP + row]         = __float2half_rn(c[mt][p][0] + b0);
                        Vh[(d+1)*VP + row]     = __float2half_rn(c[mt][p][1] + b1);
                        Vh[d*VP + row + 8]     = __float2half_rn(c[mt][p][2] + b0);
                        Vh[(d+1)*VP + row + 8] = __float2half_rn(c[mt][p][3] + b1);
                    }
                }
            }
        }
        __syncthreads();

        if (wi + 1 < NW) gather_regs(widx + 1);

        // ---- attention: warp = (head, 16-row quarter) ----
        {
            const int h = wid >> 2, r0 = (wid & 3) * 16;
            const __half* Qh = Qs + h*64*QP;
            const __half* Kh = Ks + h*64*QP;
            const __half* Vh = Vt + h*32*VP;
            const unsigned qBase = s2u(Qh) + ((r0 + rA)*QP + cA) * 2;
            const unsigned kBase = s2u(Kh) + (rB*QP + cB) * 2;
            const unsigned vBase = s2u(Vh) + (rB*VP + cB) * 2;

            float s[8][4];
            #pragma unroll
            for (int nt = 0; nt < 8; ++nt)
                s[nt][0] = s[nt][1] = s[nt][2] = s[nt][3] = 0.f;

            #pragma unroll
            for (int kt = 0; kt < 2; ++kt) {
                int k0 = kt * 16;
                unsigned a[4];
                ldsm_x4(a[0], a[1], a[2], a[3], qBase + k0*2);
                #pragma unroll
                for (int ntp = 0; ntp < 4; ++ntp) {
                    unsigned bf[4];
                    ldsm_x4(bf[0], bf[1], bf[2], bf[3], kBase + (ntp*16*QP + k0)*2);
                    mma_f16(s[2*ntp][0], s[2*ntp][1], s[2*ntp][2], s[2*ntp][3],
                            a[0], a[1], a[2], a[3], bf[0], bf[1]);
                    mma_f16(s[2*ntp+1][0], s[2*ntp+1][1], s[2*ntp+1][2], s[2*ntp+1][3],
                            a[0], a[1], a[2], a[3], bf[2], bf[3]);
                }
            }

            // softmax with register bias
            #pragma unroll
            for (int rr = 0; rr < 2; ++rr) {
                float m = -1e30f;
                #pragma unroll
                for (int nt = 0; nt < 8; ++nt) {
                    float2 bb = __half22float2(barr[rr][nt]);
                    float v0 = s[nt][rr*2+0] * scale + bb.x;
                    float v1 = s[nt][rr*2+1] * scale + bb.y;
                    s[nt][rr*2+0] = v0; s[nt][rr*2+1] = v1;
                    m = fmaxf(m, fmaxf(v0, v1));
                }
                m = fmaxf(m, __shfl_xor_sync(0xffffffffu, m, 1));
                m = fmaxf(m, __shfl_xor_sync(0xffffffffu, m, 2));
                float sum = 0.f;
                #pragma unroll
                for (int nt = 0; nt < 8; ++nt) {
                    float e0 = __expf(s[nt][rr*2+0] - m);
                    float e1 = __expf(s[nt][rr*2+1] - m);
                    s[nt][rr*2+0] = e0; s[nt][rr*2+1] = e1;
                    sum += e0 + e1;
                }
                sum += __shfl_xor_sync(0xffffffffu, sum, 1);
                sum += __shfl_xor_sync(0xffffffffu, sum, 2);
                float inv = 1.0f / sum;
                #pragma unroll
                for (int nt = 0; nt < 8; ++nt) {
                    s[nt][rr*2+0] *= inv;
                    s[nt][rr*2+1] *= inv;
                }
            }

            unsigned af[4][4];
            #pragma unroll
            for (int kt = 0; kt < 4; ++kt) {
                __half2 h0 = __floats2half2_rn(s[2*kt][0],   s[2*kt][1]);
                __half2 h1 = __floats2half2_rn(s[2*kt][2],   s[2*kt][3]);
                __half2 h2 = __floats2half2_rn(s[2*kt+1][0], s[2*kt+1][1]);
                __half2 h3 = __floats2half2_rn(s[2*kt+1][2], s[2*kt+1][3]);
                af[kt][0] = *reinterpret_cast<unsigned*>(&h0);
                af[kt][1] = *reinterpret_cast<unsigned*>(&h1);
                af[kt][2] = *reinterpret_cast<unsigned*>(&h2);
                af[kt][3] = *reinterpret_cast<unsigned*>(&h3);
            }

            float o[4][4];
            #pragma unroll
            for (int nt = 0; nt < 4; ++nt)
                o[nt][0] = o[nt][1] = o[nt][2] = o[nt][3] = 0.f;

            #pragma unroll
            for (int kt = 0; kt < 4; ++kt) {
                #pragma unroll
                for (int ntp = 0; ntp < 2; ++ntp) {
                    unsigned bf[4];
                    ldsm_x4(bf[0], bf[1], bf[2], bf[3], vBase + (ntp*16*VP + kt*16)*2);
                    mma_f16(o[2*ntp][0], o[2*ntp][1], o[2*ntp][2], o[2*ntp][3],
                            af[kt][0], af[kt][1], af[kt][2], af[kt][3], bf[0], bf[1]);
                    mma_f16(o[2*ntp+1][0], o[2*ntp+1][1], o[2*ntp+1][2], o[2*ntp+1][3],
                            af[kt][0], af[kt][1], af[kt][2], af[kt][3], bf[2], bf[3]);
                }
            }
            #pragma unroll
            for (int nt = 0; nt < 4; ++nt) {
                int col = h*32 + nt*8 + 2*tg;
                int row = r0 + g;
                *reinterpret_cast<__half2*>(Xs + row*XP + col) =
                    __floats2half2_rn(o[nt][0], o[nt][1]);
                *reinterpret_cast<__half2*>(Xs + (row+8)*XP + col) =
                    __floats2half2_rn(o[nt][2], o[nt][3]);
            }
        }
        __syncthreads();

        // ---- proj: warp = 16 rows x 32 cols; scatter store ----
        {
            const int mh = wid >> 2, nq = wid & 3;
            const unsigned aBase = s2u(Xs) + ((mh*16 + rA)*XP + cA) * 2;
            const unsigned bBase = s2u(Wp) + ((nq*32 + rB)*WPP + cB) * 2;

            float c[4][4];
            #pragma unroll
            for (int nt = 0; nt < 4; ++nt)
                c[nt][0] = c[nt][1] = c[nt][2] = c[nt][3] = 0.f;

            #pragma unroll
            for (int ks = 0; ks < 8; ++ks) {
                int k0 = ks * 16;
                unsigned a[4];
                ldsm_x4(a[0], a[1], a[2], a[3], aBase + k0*2);
                #pragma unroll
                for (int ntp = 0; ntp < 2; ++ntp) {
                    unsigned bf[4];
                    ldsm_x4(bf[0], bf[1], bf[2], bf[3], bBase + (ntp*16*WPP + k0)*2);
                    mma_f16(c[2*ntp][0], c[2*ntp][1], c[2*ntp][2], c[2*ntp][3],
                            a[0], a[1], a[2], a[3], bf[0], bf[1]);
                    mma_f16(c[2*ntp+1][0], c[2*ntp+1][1], c[2*ntp+1][2], c[2*ntp+1][3],
                            a[0], a[1], a[2], a[3], bf[2], bf[3]);
                }
            }
            #pragma unroll
            for (int nt = 0; nt < 4; ++nt) {
                int col = nq*32 + nt*8 + 2*tg;
                float b0 = pb[col], b1 = pb[col + 1];
                #pragma unroll
                for (int rr = 0; rr < 2; ++rr) {
                    int t = mh*16 + g + rr*8;
                    int i = t >> 3, j = t & 7;
                    int gr = (wh*8 + i + SHIFTV) & 511;
                    int gc = (ww*8 + j + SHIFTV) & 511;
                    float2 st;
                    st.x = c[nt][rr*2+0] + b0;
                    st.y = c[nt][rr*2+1] + b1;
                    *reinterpret_cast<float2*>(
                        out + (((size_t)b*512 + gr)*512 + gc)*128 + col) = st;
                }
            }
        }
    }
}

extern "C" void kernel_launch(void* const* d_in, const int* in_sizes, int n_in,
                              void* d_out, int out_size)
{
    const float* x          = (const float*)d_in[0];
    const float* qkv_w      = (const float*)d_in[1];
    const float* qkv_b      = (const float*)d_in[2];
    const float* proj_w     = (const float*)d_in[3];
    const float* proj_b     = (const float*)d_in[4];
    const float* bias_table = (const float*)d_in[5];
    float* out = (float*)d_out;

    cudaFuncSetAttribute(swin_win_attn_kernel,
                         cudaFuncAttributeMaxDynamicSharedMemorySize, SMEM_BYTES);
    swin_win_attn_kernel<<<16384/NW, NTHREADS, SMEM_BYTES>>>(
        x, qkv_w, qkv_b, proj_w, proj_b, bias_table, out);
}

// round 9
// speedup vs baseline: 1.3055x; 1.0532x over previous
#include <cuda_runtime.h>
#include <cuda_fp16.h>

#define SHIFTV 4
#define HEADS 4
#define NW 16
#define NTHREADS 256

#define XP 136
#define WQP 136
#define WPP 136
#define QP 40
#define VP 72

#define H_WQ (384*WQP)
#define H_WP (128*WPP)
#define H_X  (64*XP)
#define H_Q  (HEADS*64*QP)
#define H_K  (HEADS*64*QP)
#define H_V  (HEADS*32*VP)
#define SMEM_HALVES (H_WQ+H_WP+H_X+H_Q+H_K+H_V)
#define SMEM_BYTES  (SMEM_HALVES*2 + (384+128)*4)

__device__ __forceinline__ void mma_f16(float& c0, float& c1, float& c2, float& c3,
                                        unsigned a0, unsigned a1, unsigned a2, unsigned a3,
                                        unsigned b0, unsigned b1) {
    asm volatile(
        "mma.sync.aligned.m16n8k16.row.col.f32.f16.f16.f32 "
        "{%0,%1,%2,%3},{%4,%5,%6,%7},{%8,%9},{%0,%1,%2,%3};\n"
        : "+f"(c0), "+f"(c1), "+f"(c2), "+f"(c3)
        : "r"(a0), "r"(a1), "r"(a2), "r"(a3), "r"(b0), "r"(b1));
}
__device__ __forceinline__ void ldsm_x4(unsigned& r0, unsigned& r1,
                                        unsigned& r2, unsigned& r3, unsigned addr) {
    asm volatile("ldmatrix.sync.aligned.m8n8.x4.shared.b16 {%0,%1,%2,%3}, [%4];\n"
                 : "=r"(r0), "=r"(r1), "=r"(r2), "=r"(r3) : "r"(addr));
}
__device__ __forceinline__ unsigned s2u(const void* p) {
    return (unsigned)__cvta_generic_to_shared(p);
}
__device__ __forceinline__ int bidx(int i, int j) {
    return ((i >> 3) - (j >> 3) + 7) * 15 + ((i & 7) - (j & 7) + 7);
}

__global__ __launch_bounds__(NTHREADS, 1) void swin_win_attn_kernel(
    const float* __restrict__ x, const float* __restrict__ qkv_w,
    const float* __restrict__ qkv_b, const float* __restrict__ proj_w,
    const float* __restrict__ proj_b, const float* __restrict__ bias_table,
    float* __restrict__ out)
{
    extern __shared__ char smem_raw[];
    __half* Wq = reinterpret_cast<__half*>(smem_raw);
    __half* Wp = Wq + H_WQ;
    __half* Xs = Wp + H_WP;
    __half* Qs = Xs + H_X;
    __half* Ks = Qs + H_Q;
    __half* Vt = Ks + H_K;
    float*  qb = reinterpret_cast<float*>(Vt + H_V);
    float*  pb = qb + 384;

    const int tid = threadIdx.x, lane = tid & 31, wid = tid >> 5;
    const int g = lane >> 2, tg = lane & 3;

    const int rA = ((lane >> 3) & 1) * 8 + (lane & 7);
    const int cA = (lane >> 4) * 8;
    const int rB = ((lane >> 4) & 1) * 8 + (lane & 7);
    const int cB = ((lane >> 3) & 1) * 8;

    // ---- one-time: weights fp32->fp16 transposed into SMEM ----
    for (int i = tid; i < 128*96; i += NTHREADS) {
        int k = i / 96, n4 = (i % 96) * 4;
        float4 v = *reinterpret_cast<const float4*>(qkv_w + k*384 + n4);
        Wq[(n4+0)*WQP + k] = __float2half_rn(v.x);
        Wq[(n4+1)*WQP + k] = __float2half_rn(v.y);
        Wq[(n4+2)*WQP + k] = __float2half_rn(v.z);
        Wq[(n4+3)*WQP + k] = __float2half_rn(v.w);
    }
    for (int i = tid; i < 128*32; i += NTHREADS) {
        int k = i >> 5, n4 = (i & 31) * 4;
        float4 v = *reinterpret_cast<const float4*>(proj_w + k*128 + n4);
        Wp[(n4+0)*WPP + k] = __float2half_rn(v.x);
        Wp[(n4+1)*WPP + k] = __float2half_rn(v.y);
        Wp[(n4+2)*WPP + k] = __float2half_rn(v.z);
        Wp[(n4+3)*WPP + k] = __float2half_rn(v.w);
    }
    for (int i = tid; i < 384; i += NTHREADS) qb[i] = qkv_b[i];
    if (tid < 128) pb[tid] = proj_b[tid];

    // ---- one-time: bias fragment; attn warp = (head=wid>>1, 32-row half) ----
    __half2 barr[2][2][8];
    {
        int h = wid >> 1, r0 = (wid & 1) * 32;
        #pragma unroll
        for (int mt = 0; mt < 2; ++mt)
            #pragma unroll
            for (int rr = 0; rr < 2; ++rr)
                #pragma unroll
                for (int nt = 0; nt < 8; ++nt) {
                    int row = r0 + mt*16 + g + rr*8, c0 = nt*8 + 2*tg;
                    barr[mt][rr][nt] = __floats2half2_rn(
                        bias_table[bidx(row, c0)*HEADS + h],
                        bias_table[bidx(row, c0+1)*HEADS + h]);
                }
    }

    const float scale = 0.17677669529663687f;

    // register-pipelined gather: 8 tokens x 8 halves per thread
    unsigned hreg[16];
    const int c4 = lane * 4;
    auto gather_regs = [&](int widx) {
        int bb = widx >> 12, wh = (widx >> 6) & 63, ww = widx & 63;
        #pragma unroll
        for (int k = 0; k < 8; ++k) {
            int t = wid + k * 8;
            int i = t >> 3, j = t & 7;
            int gr = (wh*8 + i + SHIFTV) & 511;
            int gc = (ww*8 + j + SHIFTV) & 511;
            float4 v = *reinterpret_cast<const float4*>(
                x + (((size_t)bb*512 + gr)*512 + gc)*128 + c4);
            __half2 h0 = __floats2half2_rn(v.x, v.y);
            __half2 h1 = __floats2half2_rn(v.z, v.w);
            hreg[k*2]   = *reinterpret_cast<unsigned*>(&h0);
            hreg[k*2+1] = *reinterpret_cast<unsigned*>(&h1);
        }
    };
    auto store_regs = [&]() {
        #pragma unroll
        for (int k = 0; k < 8; ++k) {
            int t = wid + k * 8;
            *reinterpret_cast<unsigned*>(Xs + t*XP + c4)     = hreg[k*2];
            *reinterpret_cast<unsigned*>(Xs + t*XP + c4 + 2) = hreg[k*2+1];
        }
    };

    gather_regs(blockIdx.x * NW);

    for (int wi = 0; wi < NW; ++wi) {
        const int widx = blockIdx.x * NW + wi;
        const int b = widx >> 12, wh = (widx >> 6) & 63, ww = widx & 63;

        __syncthreads();
        store_regs();
        __syncthreads();

        // ---- QKV: warp = 64 rows x 48 cols (8 warps cover 384 cols) ----
        {
            const int cb = wid * 48;
            const unsigned aBase = s2u(Xs) + (rA*XP + cA) * 2;
            const unsigned bBase = s2u(Wq) + ((cb + rB)*WQP + cB) * 2;

            float c[4][6][4];
            #pragma unroll
            for (int mt = 0; mt < 4; ++mt)
                #pragma unroll
                for (int p = 0; p < 6; ++p)
                    c[mt][p][0] = c[mt][p][1] = c[mt][p][2] = c[mt][p][3] = 0.f;

            #pragma unroll
            for (int ks = 0; ks < 8; ++ks) {
                int k0 = ks * 16;
                unsigned a[4][4];
                #pragma unroll
                for (int mt = 0; mt < 4; ++mt)
                    ldsm_x4(a[mt][0], a[mt][1], a[mt][2], a[mt][3],
                            aBase + (mt*16*XP + k0)*2);
                #pragma unroll
                for (int pp = 0; pp < 3; ++pp) {
                    unsigned bf[4];
                    ldsm_x4(bf[0], bf[1], bf[2], bf[3], bBase + (pp*16*WQP + k0)*2);
                    #pragma unroll
                    for (int mt = 0; mt < 4; ++mt) {
                        mma_f16(c[mt][2*pp][0], c[mt][2*pp][1], c[mt][2*pp][2], c[mt][2*pp][3],
                                a[mt][0], a[mt][1], a[mt][2], a[mt][3], bf[0], bf[1]);
                        mma_f16(c[mt][2*pp+1][0], c[mt][2*pp+1][1], c[mt][2*pp+1][2], c[mt][2*pp+1][3],
                                a[mt][0], a[mt][1], a[mt][2], a[mt][3], bf[2], bf[3]);
                    }
                }
            }
            #pragma unroll
            for (int p = 0; p < 6; ++p) {
                int col = cb + p*8 + 2*tg;
                int mat = col >> 7, head = (col >> 5) & 3, d = col & 31;
                float b0 = qb[col], b1 = qb[col + 1];
                #pragma unroll
                for (int mt = 0; mt < 4; ++mt) {
                    int row = mt*16 + g;
                    if (mat == 0) {
                        __half* Qh = Qs + head*64*QP;
                        *reinterpret_cast<__half2*>(Qh + row*QP + d) =
                            __floats2half2_rn(c[mt][p][0] + b0, c[mt][p][1] + b1);
                        *reinterpret_cast<__half2*>(Qh + (row+8)*QP + d) =
                            __floats2half2_rn(c[mt][p][2] + b0, c[mt][p][3] + b1);
                    } else if (mat == 1) {
                        __half* Kh = Ks + head*64*QP;
                        *reinterpret_cast<__half2*>(Kh + row*QP + d) =
                            __floats2half2_rn(c[mt][p][0] + b0, c[mt][p][1] + b1);
                        *reinterpret_cast<__half2*>(Kh + (row+8)*QP + d) =
                            __floats2half2_rn(c[mt][p][2] + b0, c[mt][p][3] + b1);
                    } else {
                        __half* Vh = Vt + head*32*VP;
                        Vh[d*VP + row]         = __float2half_rn(c[mt][p][0] + b0);
                        Vh[(d+1)*VP + row]     = __float2half_rn(c[mt][p][1] + b1);
                        Vh[d*VP + row + 8]     = __float2half_rn(c[mt][p][2] + b0);
                        Vh[(d+1)*VP + row + 8] = __float2half_rn(c[mt][p][3] + b1);
                    }
                }
            }
        }
        __syncthreads();

        if (wi + 1 < NW) gather_regs(widx + 1);

        // ---- attention: warp = (head, 32-row half) ----
        {
            const int h = wid >> 1, r0 = (wid & 1) * 32;
            const __half* Qh = Qs + h*64*QP;
            const __half* Kh = Ks + h*64*QP;
            const __half* Vh = Vt + h*32*VP;
            const unsigned qBase = s2u(Qh) + ((r0 + rA)*QP + cA) * 2;
            const unsigned kBase = s2u(Kh) + (rB*QP + cB) * 2;
            const unsigned vBase = s2u(Vh) + (rB*VP + cB) * 2;

            float s[2][8][4];
            #pragma unroll
            for (int mt = 0; mt < 2; ++mt)
                #pragma unroll
                for (int nt = 0; nt < 8; ++nt)
                    s[mt][nt][0] = s[mt][nt][1] = s[mt][nt][2] = s[mt][nt][3] = 0.f;

            #pragma unroll
            for (int kt = 0; kt < 2; ++kt) {
                int k0 = kt * 16;
                unsigned a[2][4];
                ldsm_x4(a[0][0], a[0][1], a[0][2], a[0][3], qBase + k0*2);
                ldsm_x4(a[1][0], a[1][1], a[1][2], a[1][3], qBase + (16*QP + k0)*2);
                #pragma unroll
                for (int ntp = 0; ntp < 4; ++ntp) {
                    unsigned bf[4];
                    ldsm_x4(bf[0], bf[1], bf[2], bf[3], kBase + (ntp*16*QP + k0)*2);
                    #pragma unroll
                    for (int mt = 0; mt < 2; ++mt) {
                        mma_f16(s[mt][2*ntp][0], s[mt][2*ntp][1], s[mt][2*ntp][2], s[mt][2*ntp][3],
                                a[mt][0], a[mt][1], a[mt][2], a[mt][3], bf[0], bf[1]);
                        mma_f16(s[mt][2*ntp+1][0], s[mt][2*ntp+1][1], s[mt][2*ntp+1][2], s[mt][2*ntp+1][3],
                                a[mt][0], a[mt][1], a[mt][2], a[mt][3], bf[2], bf[3]);
                    }
                }
            }

            // softmax with register bias
            #pragma unroll
            for (int mt = 0; mt < 2; ++mt)
                #pragma unroll
                for (int rr = 0; rr < 2; ++rr) {
                    float m = -1e30f;
                    #pragma unroll
                    for (int nt = 0; nt < 8; ++nt) {
                        float2 bb = __half22float2(barr[mt][rr][nt]);
                        float v0 = s[mt][nt][rr*2+0] * scale + bb.x;
                        float v1 = s[mt][nt][rr*2+1] * scale + bb.y;
                        s[mt][nt][rr*2+0] = v0; s[mt][nt][rr*2+1] = v1;
                        m = fmaxf(m, fmaxf(v0, v1));
                    }
                    m = fmaxf(m, __shfl_xor_sync(0xffffffffu, m, 1));
                    m = fmaxf(m, __shfl_xor_sync(0xffffffffu, m, 2));
                    float sum = 0.f;
                    #pragma unroll
                    for (int nt = 0; nt < 8; ++nt) {
                        float e0 = __expf(s[mt][nt][rr*2+0] - m);
                        float e1 = __expf(s[mt][nt][rr*2+1] - m);
                        s[mt][nt][rr*2+0] = e0; s[mt][nt][rr*2+1] = e1;
                        sum += e0 + e1;
                    }
                    sum += __shfl_xor_sync(0xffffffffu, sum, 1);
                    sum += __shfl_xor_sync(0xffffffffu, sum, 2);
                    float inv = 1.0f / sum;
                    #pragma unroll
                    for (int nt = 0; nt < 8; ++nt) {
                        s[mt][nt][rr*2+0] *= inv;
                        s[mt][nt][rr*2+1] *= inv;
                    }
                }

            // repack probs as A-frags
            unsigned af[2][4][4];
            #pragma unroll
            for (int mt = 0; mt < 2; ++mt)
                #pragma unroll
                for (int kt = 0; kt < 4; ++kt) {
                    __half2 h0 = __floats2half2_rn(s[mt][2*kt][0],   s[mt][2*kt][1]);
                    __half2 h1 = __floats2half2_rn(s[mt][2*kt][2],   s[mt][2*kt][3]);
                    __half2 h2 = __floats2half2_rn(s[mt][2*kt+1][0], s[mt][2*kt+1][1]);
                    __half2 h3 = __floats2half2_rn(s[mt][2*kt+1][2], s[mt][2*kt+1][3]);
                    af[mt][kt][0] = *reinterpret_cast<unsigned*>(&h0);
                    af[mt][kt][1] = *reinterpret_cast<unsigned*>(&h1);
                    af[mt][kt][2] = *reinterpret_cast<unsigned*>(&h2);
                    af[mt][kt][3] = *reinterpret_cast<unsigned*>(&h3);
                }

            float o[2][4][4];
            #pragma unroll
            for (int mt = 0; mt < 2; ++mt)
                #pragma unroll
                for (int nt = 0; nt < 4; ++nt)
                    o[mt][nt][0] = o[mt][nt][1] = o[mt][nt][2] = o[mt][nt][3] = 0.f;

            #pragma unroll
            for (int kt = 0; kt < 4; ++kt) {
                #pragma unroll
                for (int ntp = 0; ntp < 2; ++ntp) {
                    unsigned bf[4];
                    ldsm_x4(bf[0], bf[1], bf[2], bf[3], vBase + (ntp*16*VP + kt*16)*2);
                    #pragma unroll
                    for (int mt = 0; mt < 2; ++mt) {
                        mma_f16(o[mt][2*ntp][0], o[mt][2*ntp][1], o[mt][2*ntp][2], o[mt][2*ntp][3],
                                af[mt][kt][0], af[mt][kt][1], af[mt][kt][2], af[mt][kt][3],
                                bf[0], bf[1]);
                        mma_f16(o[mt][2*ntp+1][0], o[mt][2*ntp+1][1], o[mt][2*ntp+1][2], o[mt][2*ntp+1][3],
                                af[mt][kt][0], af[mt][kt][1], af[mt][kt][2], af[mt][kt][3],
                                bf[2], bf[3]);
                    }
                }
            }
            #pragma unroll
            for (int mt = 0; mt < 2; ++mt)
                #pragma unroll
                for (int nt = 0; nt < 4; ++nt) {
                    int col = h*32 + nt*8 + 2*tg;
                    int row = r0 + mt*16 + g;
                    *reinterpret_cast<__half2*>(Xs + row*XP + col) =
                        __floats2half2_rn(o[mt][nt][0], o[mt][nt][1]);
                    *reinterpret_cast<__half2*>(Xs + (row+8)*XP + col) =
                        __floats2half2_rn(o[mt][nt][2], o[mt][nt][3]);
                }
        }
        __syncthreads();

        // ---- proj: warp = 32 rows x 32 cols; scatter store ----
        {
            const int mh = wid >> 2, nq = wid & 3;
            const unsigned aBase = s2u(Xs) + ((mh*32 + rA)*XP + cA) * 2;
            const unsigned bBase = s2u(Wp) + ((nq*32 + rB)*WPP + cB) * 2;

            float c[2][4][4];
            #pragma unroll
            for (int mt = 0; mt < 2; ++mt)
                #pragma unroll
                for (int nt = 0; nt < 4; ++nt)
                    c[mt][nt][0] = c[mt][nt][1] = c[mt][nt][2] = c[mt][nt][3] = 0.f;

            #pragma unroll
            for (int ks = 0; ks < 8; ++ks) {
                int k0 = ks * 16;
                unsigned a[2][4];
                ldsm_x4(a[0][0], a[0][1], a[0][2], a[0][3], aBase + k0*2);
                ldsm_x4(a[1][0], a[1][1], a[1][2], a[1][3], aBase + (16*XP + k0)*2);
                #pragma unroll
                for (int ntp = 0; ntp < 2; ++ntp) {
                    unsigned bf[4];
                    ldsm_x4(bf[0], bf[1], bf[2], bf[3], bBase + (ntp*16*WPP + k0)*2);
                    #pragma unroll
                    for (int mt = 0; mt < 2; ++mt) {
                        mma_f16(c[mt][2*ntp][0], c[mt][2*ntp][1], c[mt][2*ntp][2], c[mt][2*ntp][3],
                                a[mt][0], a[mt][1], a[mt][2], a[mt][3], bf[0], bf[1]);
                        mma_f16(c[mt][2*ntp+1][0], c[mt][2*ntp+1][1], c[mt][2*ntp+1][2], c[mt][2*ntp+1][3],
                                a[mt][0], a[mt][1], a[mt][2], a[mt][3], bf[2], bf[3]);
                    }
                }
            }
            #pragma unroll
            for (int mt = 0; mt < 2; ++mt)
                #pragma unroll
                for (int nt = 0; nt < 4; ++nt) {
                    int col = nq*32 + nt*8 + 2*tg;
                    float b0 = pb[col], b1 = pb[col + 1];
                    #pragma unroll
                    for (int rr = 0; rr < 2; ++rr) {
                        int t = mh*32 + mt*16 + g + rr*8;
                        int i = t >> 3, j = t & 7;
                        int gr = (wh*8 + i + SHIFTV) & 511;
                        int gc = (ww*8 + j + SHIFTV) & 511;
                        float2 st;
                        st.x = c[mt][nt][rr*2+0] + b0;
                        st.y = c[mt][nt][rr*2+1] + b1;
                        *reinterpret_cast<float2*>(
                            out + (((size_t)b*512 + gr)*512 + gc)*128 + col) = st;
                    }
                }
        }
    }
}

extern "C" void kernel_launch(void* const* d_in, const int* in_sizes, int n_in,
                              void* d_out, int out_size)
{
    const float* x          = (const float*)d_in[0];
    const float* qkv_w      = (const float*)d_in[1];
    const float* qkv_b      = (const float*)d_in[2];
    const float* proj_w     = (const float*)d_in[3];
    const float* proj_b     = (const float*)d_in[4];
    const float* bias_table = (const float*)d_in[5];
    float* out = (float*)d_out;

    cudaFuncSetAttribute(swin_win_attn_kernel,
                         cudaFuncAttributeMaxDynamicSharedMemorySize, SMEM_BYTES);
    swin_win_attn_kernel<<<16384/NW, NTHREADS, SMEM_BYTES>>>(
        x, qkv_w, qkv_b, proj_w, proj_b, bias_table, out);
}

// round 14
// speedup vs baseline: 1.3559x; 1.0386x over previous
#include <cuda_runtime.h>
#include <cuda_fp16.h>

#define SHIFTV 4
#define HEADS 4
#define NW 16
#define NTHREADS 256

#define XP 136
#define WQP 136
#define WPP 136
#define QP 40
#define VP 72

#define H_WQ (384*WQP)
#define H_WP (128*WPP)
#define H_X  (64*XP)
#define H_Q  (HEADS*64*QP)
#define H_K  (HEADS*64*QP)
#define H_V  (HEADS*32*VP)
#define SMEM_HALVES (H_WQ+H_WP+H_X+H_Q+H_K+H_V)
#define SMEM_BYTES  (SMEM_HALVES*2 + (384+128)*4)

__device__ __forceinline__ void mma_f16(float& c0, float& c1, float& c2, float& c3,
                                        unsigned a0, unsigned a1, unsigned a2, unsigned a3,
                                        unsigned b0, unsigned b1) {
    asm volatile(
        "mma.sync.aligned.m16n8k16.row.col.f32.f16.f16.f32 "
        "{%0,%1,%2,%3},{%4,%5,%6,%7},{%8,%9},{%0,%1,%2,%3};\n"
        : "+f"(c0), "+f"(c1), "+f"(c2), "+f"(c3)
        : "r"(a0), "r"(a1), "r"(a2), "r"(a3), "r"(b0), "r"(b1));
}
__device__ __forceinline__ void ldsm_x4(unsigned& r0, unsigned& r1,
                                        unsigned& r2, unsigned& r3, unsigned addr) {
    asm volatile("ldmatrix.sync.aligned.m8n8.x4.shared.b16 {%0,%1,%2,%3}, [%4];\n"
                 : "=r"(r0), "=r"(r1), "=r"(r2), "=r"(r3) : "r"(addr));
}
__device__ __forceinline__ unsigned s2u(const void* p) {
    return (unsigned)__cvta_generic_to_shared(p);
}
__device__ __forceinline__ int bidx(int i, int j) {
    return ((i >> 3) - (j >> 3) + 7) * 15 + ((i & 7) - (j & 7) + 7);
}

__global__ __launch_bounds__(NTHREADS, 1) void swin_win_attn_kernel(
    const float* __restrict__ x, const float* __restrict__ qkv_w,
    const float* __restrict__ qkv_b, const float* __restrict__ proj_w,
    const float* __restrict__ proj_b, const float* __restrict__ bias_table,
    float* __restrict__ out)
{
    extern __shared__ char smem_raw[];
    __half* Wq = reinterpret_cast<__half*>(smem_raw);
    __half* Wp = Wq + H_WQ;
    __half* Xs = Wp + H_WP;
    __half* Qs = Xs + H_X;
    __half* Ks = Qs + H_Q;
    __half* Vt = Ks + H_K;
    float*  qb = reinterpret_cast<float*>(Vt + H_V);
    float*  pb = qb + 384;

    const int tid = threadIdx.x, lane = tid & 31, wid = tid >> 5;
    const int g = lane >> 2, tg = lane & 3;

    const int rA = ((lane >> 3) & 1) * 8 + (lane & 7);
    const int cA = (lane >> 4) * 8;
    const int rB = ((lane >> 4) & 1) * 8 + (lane & 7);
    const int cB = ((lane >> 3) & 1) * 8;

    // ---- one-time: weights fp32->fp16 transposed into SMEM ----
    for (int i = tid; i < 128*96; i += NTHREADS) {
        int k = i / 96, n4 = (i % 96) * 4;
        float4 v = *reinterpret_cast<const float4*>(qkv_w + k*384 + n4);
        Wq[(n4+0)*WQP + k] = __float2half_rn(v.x);
        Wq[(n4+1)*WQP + k] = __float2half_rn(v.y);
        Wq[(n4+2)*WQP + k] = __float2half_rn(v.z);
        Wq[(n4+3)*WQP + k] = __float2half_rn(v.w);
    }
    for (int i = tid; i < 128*32; i += NTHREADS) {
        int k = i >> 5, n4 = (i & 31) * 4;
        float4 v = *reinterpret_cast<const float4*>(proj_w + k*128 + n4);
        Wp[(n4+0)*WPP + k] = __float2half_rn(v.x);
        Wp[(n4+1)*WPP + k] = __float2half_rn(v.y);
        Wp[(n4+2)*WPP + k] = __float2half_rn(v.z);
        Wp[(n4+3)*WPP + k] = __float2half_rn(v.w);
    }
    for (int i = tid; i < 384; i += NTHREADS) qb[i] = qkv_b[i];
    if (tid < 128) pb[tid] = proj_b[tid];
    __syncthreads();   // weights visible for B-fragment caching

    // ---- one-time: QKV B-fragments into registers (persist across windows) ----
    const int cbW = wid * 48;
    unsigned bq[8][3][4];
    {
        const unsigned bBase = s2u(Wq) + ((cbW + rB)*WQP + cB) * 2;
        #pragma unroll
        for (int ks = 0; ks < 8; ++ks)
            #pragma unroll
            for (int pp = 0; pp < 3; ++pp)
                ldsm_x4(bq[ks][pp][0], bq[ks][pp][1], bq[ks][pp][2], bq[ks][pp][3],
                        bBase + (pp*16*WQP + ks*16)*2);
    }

    // ---- one-time: bias fragment; attn warp = (head=wid>>1, 32-row half) ----
    __half2 barr[2][2][8];
    {
        int h = wid >> 1, r0 = (wid & 1) * 32;
        #pragma unroll
        for (int mt = 0; mt < 2; ++mt)
            #pragma unroll
            for (int rr = 0; rr < 2; ++rr)
                #pragma unroll
                for (int nt = 0; nt < 8; ++nt) {
                    int row = r0 + mt*16 + g + rr*8, c0 = nt*8 + 2*tg;
                    barr[mt][rr][nt] = __floats2half2_rn(
                        bias_table[bidx(row, c0)*HEADS + h],
                        bias_table[bidx(row, c0+1)*HEADS + h]);
                }
    }

    const float scale = 0.17677669529663687f;

    unsigned hreg[16];
    const int c4 = lane * 4;
    auto gather_regs = [&](int widx) {
        int bb = widx >> 12, wh = (widx >> 6) & 63, ww = widx & 63;
        #pragma unroll
        for (int k = 0; k < 8; ++k) {
            int t = wid + k * 8;
            int i = t >> 3, j = t & 7;
            int gr = (wh*8 + i + SHIFTV) & 511;
            int gc = (ww*8 + j + SHIFTV) & 511;
            float4 v = *reinterpret_cast<const float4*>(
                x + (((size_t)bb*512 + gr)*512 + gc)*128 + c4);
            __half2 h0 = __floats2half2_rn(v.x, v.y);
            __half2 h1 = __floats2half2_rn(v.z, v.w);
            hreg[k*2]   = *reinterpret_cast<unsigned*>(&h0);
            hreg[k*2+1] = *reinterpret_cast<unsigned*>(&h1);
        }
    };
    auto store_regs = [&]() {
        #pragma unroll
        for (int k = 0; k < 8; ++k) {
            int t = wid + k * 8;
            *reinterpret_cast<unsigned*>(Xs + t*XP + c4)     = hreg[k*2];
            *reinterpret_cast<unsigned*>(Xs + t*XP + c4 + 2) = hreg[k*2+1];
        }
    };

    gather_regs(blockIdx.x * NW);

    for (int wi = 0; wi < NW; ++wi) {
        const int widx = blockIdx.x * NW + wi;
        const int b = widx >> 12, wh = (widx >> 6) & 63, ww = widx & 63;

        __syncthreads();
        store_regs();
        __syncthreads();

        // ---- QKV: warp = 48 cols, M processed in two 32-row halves ----
        #pragma unroll
        for (int mh = 0; mh < 2; ++mh) {
            const unsigned aBase = s2u(Xs) + ((mh*32 + rA)*XP + cA) * 2;
            float c[2][6][4];
            #pragma unroll
            for (int mt = 0; mt < 2; ++mt)
                #pragma unroll
                for (int p = 0; p < 6; ++p)
                    c[mt][p][0] = c[mt][p][1] = c[mt][p][2] = c[mt][p][3] = 0.f;

            #pragma unroll
            for (int ks = 0; ks < 8; ++ks) {
                int k0 = ks * 16;
                unsigned a[2][4];
                ldsm_x4(a[0][0], a[0][1], a[0][2], a[0][3], aBase + k0*2);
                ldsm_x4(a[1][0], a[1][1], a[1][2], a[1][3], aBase + (16*XP + k0)*2);
                #pragma unroll
                for (int pp = 0; pp < 3; ++pp) {
                    #pragma unroll
                    for (int mt = 0; mt < 2; ++mt) {
                        mma_f16(c[mt][2*pp][0], c[mt][2*pp][1], c[mt][2*pp][2], c[mt][2*pp][3],
                                a[mt][0], a[mt][1], a[mt][2], a[mt][3],
                                bq[ks][pp][0], bq[ks][pp][1]);
                        mma_f16(c[mt][2*pp+1][0], c[mt][2*pp+1][1], c[mt][2*pp+1][2], c[mt][2*pp+1][3],
                                a[mt][0], a[mt][1], a[mt][2], a[mt][3],
                                bq[ks][pp][2], bq[ks][pp][3]);
                    }
                }
            }
            #pragma unroll
            for (int p = 0; p < 6; ++p) {
                int col = cbW + p*8 + 2*tg;
                int mat = col >> 7, head = (col >> 5) & 3, d = col & 31;
                float b0 = qb[col], b1 = qb[col + 1];
                #pragma unroll
                for (int mt = 0; mt < 2; ++mt) {
                    int row = mh*32 + mt*16 + g;
                    if (mat == 0) {
                        __half* Qh = Qs + head*64*QP;
                        *reinterpret_cast<__half2*>(Qh + row*QP + d) =
                            __floats2half2_rn(c[mt][p][0] + b0, c[mt][p][1] + b1);
                        *reinterpret_cast<__half2*>(Qh + (row+8)*QP + d) =
                            __floats2half2_rn(c[mt][p][2] + b0, c[mt][p][3] + b1);
                    } else if (mat == 1) {
                        __half* Kh = Ks + head*64*QP;
                        *reinterpret_cast<__half2*>(Kh + row*QP + d) =
                            __floats2half2_rn(c[mt][p][0] + b0, c[mt][p][1] + b1);
                        *reinterpret_cast<__half2*>(Kh + (row+8)*QP + d) =
                            __floats2half2_rn(c[mt][p][2] + b0, c[mt][p][3] + b1);
                    } else {
                        __half* Vh = Vt + head*32*VP;
                        Vh[d*VP + row]         = __float2half_rn(c[mt][p][0] + b0);
                        Vh[(d+1)*VP + row]     = __float2half_rn(c[mt][p][1] + b1);
                        Vh[d*VP + row + 8]     = __float2half_rn(c[mt][p][2] + b0);
                        Vh[(d+1)*VP + row + 8] = __float2half_rn(c[mt][p][3] + b1);
                    }
                }
            }
        }
        __syncthreads();

        if (wi + 1 < NW) gather_regs(widx + 1);

        // ---- attention: warp = (head, 32-row half) ----
        {
            const int h = wid >> 1, r0 = (wid & 1) * 32;
            const __half* Qh = Qs + h*64*QP;
            const __half* Kh = Ks + h*64*QP;
            const __half* Vh = Vt + h*32*VP;
            const unsigned qBase = s2u(Qh) + ((r0 + rA)*QP + cA) * 2;
            const unsigned kBase = s2u(Kh) + (rB*QP + cB) * 2;
            const unsigned vBase = s2u(Vh) + (rB*VP + cB) * 2;

            float s[2][8][4];
            #pragma unroll
            for (int mt = 0; mt < 2; ++mt)
                #pragma unroll
                for (int nt = 0; nt < 8; ++nt)
                    s[mt][nt][0] = s[mt][nt][1] = s[mt][nt][2] = s[mt][nt][3] = 0.f;

            #pragma unroll
            for (int kt = 0; kt < 2; ++kt) {
                int k0 = kt * 16;
                unsigned a[2][4];
                ldsm_x4(a[0][0], a[0][1], a[0][2], a[0][3], qBase + k0*2);
                ldsm_x4(a[1][0], a[1][1], a[1][2], a[1][3], qBase + (16*QP + k0)*2);
                #pragma unroll
                for (int ntp = 0; ntp < 4; ++ntp) {
                    unsigned bf[4];
                    ldsm_x4(bf[0], bf[1], bf[2], bf[3], kBase + (ntp*16*QP + k0)*2);
                    #pragma unroll
                    for (int mt = 0; mt < 2; ++mt) {
                        mma_f16(s[mt][2*ntp][0], s[mt][2*ntp][1], s[mt][2*ntp][2], s[mt][2*ntp][3],
                                a[mt][0], a[mt][1], a[mt][2], a[mt][3], bf[0], bf[1]);
                        mma_f16(s[mt][2*ntp+1][0], s[mt][2*ntp+1][1], s[mt][2*ntp+1][2], s[mt][2*ntp+1][3],
                                a[mt][0], a[mt][1], a[mt][2], a[mt][3], bf[2], bf[3]);
                    }
                }
            }

            #pragma unroll
            for (int mt = 0; mt < 2; ++mt)
                #pragma unroll
                for (int rr = 0; rr < 2; ++rr) {
                    float m = -1e30f;
                    #pragma unroll
                    for (int nt = 0; nt < 8; ++nt) {
                        float2 bb = __half22float2(barr[mt][rr][nt]);
                        float v0 = s[mt][nt][rr*2+0] * scale + bb.x;
                        float v1 = s[mt][nt][rr*2+1] * scale + bb.y;
                        s[mt][nt][rr*2+0] = v0; s[mt][nt][rr*2+1] = v1;
                        m = fmaxf(m, fmaxf(v0, v1));
                    }
                    m = fmaxf(m, __shfl_xor_sync(0xffffffffu, m, 1));
                    m = fmaxf(m, __shfl_xor_sync(0xffffffffu, m, 2));
                    float sum = 0.f;
                    #pragma unroll
                    for (int nt = 0; nt < 8; ++nt) {
                        float e0 = __expf(s[mt][nt][rr*2+0] - m);
                        float e1 = __expf(s[mt][nt][rr*2+1] - m);
                        s[mt][nt][rr*2+0] = e0; s[mt][nt][rr*2+1] = e1;
                        sum += e0 + e1;
                    }
                    sum += __shfl_xor_sync(0xffffffffu, sum, 1);
                    sum += __shfl_xor_sync(0xffffffffu, sum, 2);
                    float inv = 1.0f / sum;
                    #pragma unroll
                    for (int nt = 0; nt < 8; ++nt) {
                        s[mt][nt][rr*2+0] *= inv;
                        s[mt][nt][rr*2+1] *= inv;
                    }
                }

            unsigned af[2][4][4];
            #pragma unroll
            for (int mt = 0; mt < 2; ++mt)
                #pragma unroll
                for (int kt = 0; kt < 4; ++kt) {
                    __half2 h0 = __floats2half2_rn(s[mt][2*kt][0],   s[mt][2*kt][1]);
                    __half2 h1 = __floats2half2_rn(s[mt][2*kt][2],   s[mt][2*kt][3]);
                    __half2 h2 = __floats2half2_rn(s[mt][2*kt+1][0], s[mt][2*kt+1][1]);
                    __half2 h3 = __floats2half2_rn(s[mt][2*kt+1][2], s[mt][2*kt+1][3]);
                    af[mt][kt][0] = *reinterpret_cast<unsigned*>(&h0);
                    af[mt][kt][1] = *reinterpret_cast<unsigned*>(&h1);
                    af[mt][kt][2] = *reinterpret_cast<unsigned*>(&h2);
                    af[mt][kt][3] = *reinterpret_cast<unsigned*>(&h3);
                }

            float o[2][4][4];
            #pragma unroll
            for (int mt = 0; mt < 2; ++mt)
                #pragma unroll
                for (int nt = 0; nt < 4; ++nt)
                    o[mt][nt][0] = o[mt][nt][1] = o[mt][nt][2] = o[mt][nt][3] = 0.f;

            #pragma unroll
            for (int kt = 0; kt < 4; ++kt) {
                #pragma unroll
                for (int ntp = 0; ntp < 2; ++ntp) {
                    unsigned bf[4];
                    ldsm_x4(bf[0], bf[1], bf[2], bf[3], vBase + (ntp*16*VP + kt*16)*2);
                    #pragma unroll
                    for (int mt = 0; mt < 2; ++mt) {
                        mma_f16(o[mt][2*ntp][0], o[mt][2*ntp][1], o[mt][2*ntp][2], o[mt][2*ntp][3],
                                af[mt][kt][0], af[mt][kt][1], af[mt][kt][2], af[mt][kt][3],
                                bf[0], bf[1]);
                        mma_f16(o[mt][2*ntp+1][0], o[mt][2*ntp+1][1], o[mt][2*ntp+1][2], o[mt][2*ntp+1][3],
                                af[mt][kt][0], af[mt][kt][1], af[mt][kt][2], af[mt][kt][3],
                                bf[2], bf[3]);
                    }
                }
            }
            #pragma unroll
            for (int mt = 0; mt < 2; ++mt)
                #pragma unroll
                for (int nt = 0; nt < 4; ++nt) {
                    int col = h*32 + nt*8 + 2*tg;
                    int row = r0 + mt*16 + g;
                    *reinterpret_cast<__half2*>(Xs + row*XP + col) =
                        __floats2half2_rn(o[mt][nt][0], o[mt][nt][1]);
                    *reinterpret_cast<__half2*>(Xs + (row+8)*XP + col) =
                        __floats2half2_rn(o[mt][nt][2], o[mt][nt][3]);
                }
        }
        __syncthreads();

        // ---- proj: warp = 32 rows x 32 cols; scatter store ----
        {
            const int mh = wid >> 2, nq = wid & 3;
            const unsigned aBase = s2u(Xs) + ((mh*32 + rA)*XP + cA) * 2;
            const unsigned bBase = s2u(Wp) + ((nq*32 + rB)*WPP + cB) * 2;

            float c[2][4][4];
            #pragma unroll
            for (int mt = 0; mt < 2; ++mt)
                #pragma unroll
                for (int nt = 0; nt < 4; ++nt)
                    c[mt][nt][0] = c[mt][nt][1] = c[mt][nt][2] = c[mt][nt][3] = 0.f;

            #pragma unroll
            for (int ks = 0; ks < 8; ++ks) {
                int k0 = ks * 16;
                unsigned a[2][4];
                ldsm_x4(a[0][0], a[0][1], a[0][2], a[0][3], aBase + k0*2);
                ldsm_x4(a[1][0], a[1][1], a[1][2], a[1][3], aBase + (16*XP + k0)*2);
                #pragma unroll
                for (int ntp = 0; ntp < 2; ++ntp) {
                    unsigned bf[4];
                    ldsm_x4(bf[0], bf[1], bf[2], bf[3], bBase + (ntp*16*WPP + k0)*2);
                    #pragma unroll
                    for (int mt = 0; mt < 2; ++mt) {
                        mma_f16(c[mt][2*ntp][0], c[mt][2*ntp][1], c[mt][2*ntp][2], c[mt][2*ntp][3],
                                a[mt][0], a[mt][1], a[mt][2], a[mt][3], bf[0], bf[1]);
                        mma_f16(c[mt][2*ntp+1][0], c[mt][2*ntp+1][1], c[mt][2*ntp+1][2], c[mt][2*ntp+1][3],
                                a[mt][0], a[mt][1], a[mt][2], a[mt][3], bf[2], bf[3]);
                    }
                }
            }
            #pragma unroll
            for (int mt = 0; mt < 2; ++mt)
                #pragma unroll
                for (int nt = 0; nt < 4; ++nt) {
                    int col = nq*32 + nt*8 + 2*tg;
                    float b0 = pb[col], b1 = pb[col + 1];
                    #pragma unroll
                    for (int rr = 0; rr < 2; ++rr) {
                        int t = mh*32 + mt*16 + g + rr*8;
                        int i = t >> 3, j = t & 7;
                        int gr = (wh*8 + i + SHIFTV) & 511;
                        int gc = (ww*8 + j + SHIFTV) & 511;
                        float2 st;
                        st.x = c[mt][nt][rr*2+0] + b0;
                        st.y = c[mt][nt][rr*2+1] + b1;
                        *reinterpret_cast<float2*>(
                            out + (((size_t)b*512 + gr)*512 + gc)*128 + col) = st;
                    }
                }
        }
    }
}

extern "C" void kernel_launch(void* const* d_in, const int* in_sizes, int n_in,
                              void* d_out, int out_size)
{
    const float* x          = (const float*)d_in[0];
    const float* qkv_w      = (const float*)d_in[1];
    const float* qkv_b      = (const float*)d_in[2];
    const float* proj_w     = (const float*)d_in[3];
    const float* proj_b     = (const float*)d_in[4];
    const float* bias_table = (const float*)d_in[5];
    float* out = (float*)d_out;

    cudaFuncSetAttribute(swin_win_attn_kernel,
                         cudaFuncAttributeMaxDynamicSharedMemorySize, SMEM_BYTES);
    swin_win_attn_kernel<<<16384/NW, NTHREADS, SMEM_BYTES>>>(
        x, qkv_w, qkv_b, proj_w, proj_b, bias_table, out);
}